// round 3
// baseline (speedup 1.0000x reference)
#include <cuda_runtime.h>

#define NB 1024
#define PIX 784
#define ZDIM 848

// Scratch: concat buffer z = [hf(784) | x1(32) | x2(32)] per sample
__device__ float z_buf[NB * ZDIM];

// ---------------------------------------------------------------------------
// Kernel 1: TDA branches. Landscape top-k collapses to (max, min1, min2).
// ---------------------------------------------------------------------------
__global__ void __launch_bounds__(128) tda_kernel(
    const float* __restrict__ dtm1, const float* __restrict__ dtm2,
    const float* __restrict__ g1w, const float* __restrict__ g1b,
    const float* __restrict__ g2w, const float* __restrict__ g2b)
{
    int b = blockIdx.x;
    int tid = threadIdx.x;
    const float* v1 = dtm1 + b * PIX;
    const float* v2 = dtm2 + b * PIX;

    float mx1 = -1e30f, a1 = 1e30f, a2 = 1e30f;   // branch1: max, min1, min2
    float mx2 = -1e30f, c1 = 1e30f, c2 = 1e30f;   // branch2
    for (int i = tid; i < PIX; i += 128) {
        float u = v1[i];
        mx1 = fmaxf(mx1, u);
        if (u < a1) { a2 = a1; a1 = u; } else if (u < a2) a2 = u;
        float w = v2[i];
        mx2 = fmaxf(mx2, w);
        if (w < c1) { c2 = c1; c1 = w; } else if (w < c2) c2 = w;
    }
    // warp reduce (merge (min1,min2) pairs)
    #pragma unroll
    for (int off = 16; off; off >>= 1) {
        mx1 = fmaxf(mx1, __shfl_xor_sync(~0u, mx1, off));
        float o1 = __shfl_xor_sync(~0u, a1, off);
        float o2 = __shfl_xor_sync(~0u, a2, off);
        float n1 = fminf(a1, o1);
        float n2 = fminf(fmaxf(a1, o1), fminf(a2, o2));
        a1 = n1; a2 = n2;
        mx2 = fmaxf(mx2, __shfl_xor_sync(~0u, mx2, off));
        float p1 = __shfl_xor_sync(~0u, c1, off);
        float p2 = __shfl_xor_sync(~0u, c2, off);
        float q1 = fminf(c1, p1);
        float q2 = fminf(fmaxf(c1, p1), fminf(c2, p2));
        c1 = q1; c2 = q2;
    }
    __shared__ float red[4][6];
    __shared__ float fin[6];
    if ((tid & 31) == 0) {
        int w = tid >> 5;
        red[w][0] = mx1; red[w][1] = a1; red[w][2] = a2;
        red[w][3] = mx2; red[w][4] = c1; red[w][5] = c2;
    }
    __syncthreads();
    if (tid == 0) {
        float M1 = red[0][0], A1 = red[0][1], A2 = red[0][2];
        float M2 = red[0][3], C1 = red[0][4], C2 = red[0][5];
        #pragma unroll
        for (int w = 1; w < 4; w++) {
            M1 = fmaxf(M1, red[w][0]);
            float o1 = red[w][1], o2 = red[w][2];
            float n1 = fminf(A1, o1);
            float n2 = fminf(fmaxf(A1, o1), fminf(A2, o2));
            A1 = n1; A2 = n2;
            M2 = fmaxf(M2, red[w][3]);
            float p1 = red[w][4], p2 = red[w][5];
            float q1 = fminf(C1, p1);
            float q2 = fminf(fmaxf(C1, p1), fminf(C2, p2));
            C1 = q1; C2 = q2;
        }
        fin[0] = M1; fin[1] = A1; fin[2] = A2;
        fin[3] = M2; fin[4] = C1; fin[5] = C2;
    }
    __syncthreads();

    // lambda values: lam[k*32 + t] = max(0, min(tseq[t]-min_{k+1}, death-tseq[t]))
    __shared__ float lam1[64], lam2[64];
    if (tid < 64) {
        int k = tid >> 5, t = tid & 31;
        float tv1 = 0.01f + (float)t * (0.28f / 31.0f);
        float tv2 = 0.05f + (float)t * (0.25f / 31.0f);
        float m1 = k ? fin[2] : fin[1];
        float m2 = k ? fin[5] : fin[4];
        lam1[tid] = fmaxf(0.0f, fminf(tv1 - m1, fin[0] - tv1));
        lam2[tid] = fmaxf(0.0f, fminf(tv2 - m2, fin[3] - tv2));
    }
    __syncthreads();

    if (tid < 32) {
        float acc = g1b[tid];
        #pragma unroll
        for (int i = 0; i < 64; i++) acc += lam1[i] * g1w[i * 32 + tid];
        z_buf[b * ZDIM + 784 + tid] = fmaxf(acc, 0.0f);
    } else if (tid < 64) {
        int j = tid - 32;
        float acc = g2b[j];
        #pragma unroll
        for (int i = 0; i < 64; i++) acc += lam2[i] * g2w[i * 32 + j];
        z_buf[b * ZDIM + 816 + j] = fmaxf(acc, 0.0f);
    }
}

// ---------------------------------------------------------------------------
// Kernel 2: fused conv1(1->32)+ReLU+conv2(32->1)+ReLU, h1 resident in smem.
// smem layout (floats): xs[960] | h1[32*785] | w1s[288] | w2s[288] | b1s[32]
// ---------------------------------------------------------------------------
#define SMEM_FLOATS (960 + 32 * 785 + 288 + 288 + 32)

__global__ void __launch_bounds__(256) conv_kernel(
    const float* __restrict__ x,
    const float* __restrict__ w1, const float* __restrict__ b1,
    const float* __restrict__ w2, const float* __restrict__ b2)
{
    extern __shared__ float smem[];
    float* xs  = smem;                 // 30x32, halo of zeros, stride 32
    float* h1  = smem + 960;           // [c][p], stride 785 (conflict-free)
    float* w1s = h1 + 32 * 785;        // 288
    float* w2s = w1s + 288;            // 288
    float* b1s = w2s + 288;            // 32

    int b = blockIdx.x, tid = threadIdx.x;

    // load input with zero halo
    for (int i = tid; i < 960; i += 256) {
        int r = i >> 5, c = i & 31;
        float v = 0.0f;
        int rr = r - 1, cc = c - 1;
        if (rr >= 0 && rr < 28 && cc >= 0 && cc < 28)
            v = x[b * 784 + rr * 28 + cc];
        xs[i] = v;
    }
    for (int i = tid; i < 288; i += 256) { w1s[i] = w1[i]; w2s[i] = w2[i]; }
    if (tid < 32) b1s[tid] = b1[tid];
    __syncthreads();

    // conv1 + ReLU -> h1 (channel-major, stride 785)
    for (int p = tid; p < 784; p += 256) {
        int y = p / 28, xc = p - y * 28;
        float xv[9];
        #pragma unroll
        for (int dy = 0; dy < 3; dy++)
            #pragma unroll
            for (int dx = 0; dx < 3; dx++)
                xv[dy * 3 + dx] = xs[(y + dy) * 32 + (xc + dx)];
        #pragma unroll
        for (int c = 0; c < 32; c++) {
            float acc = b1s[c];
            #pragma unroll
            for (int k = 0; k < 9; k++) acc += xv[k] * w1s[k * 32 + c];
            h1[c * 785 + p] = fmaxf(acc, 0.0f);
        }
    }
    __syncthreads();

    // conv2 (32->1) + ReLU -> z_buf[:,0:784]
    float b2v = b2[0];
    for (int p = tid; p < 784; p += 256) {
        int y = p / 28, xc = p - y * 28;
        float acc = b2v;
        #pragma unroll
        for (int dy = 0; dy < 3; dy++) {
            int ny = y + dy - 1;
            if (ny < 0 || ny >= 28) continue;
            #pragma unroll
            for (int dx = 0; dx < 3; dx++) {
                int nx = xc + dx - 1;
                if (nx < 0 || nx >= 28) continue;
                const float* hp = h1 + ny * 28 + nx;
                const float* wp = w2s + (dy * 3 + dx) * 32;
                #pragma unroll
                for (int c = 0; c < 32; c++)
                    acc += hp[c * 785] * wp[c];
            }
        }
        z_buf[b * ZDIM + p] = fmaxf(acc, 0.0f);
    }
}

// ---------------------------------------------------------------------------
// Kernel 3: MLP head. 8 samples/block, 256 threads.
//   fc1: j = tid&63, group = tid>>6 handles 2 samples (register blocked),
//        weight row w[i*64+j] loaded once, used for both samples.
//   fc2: 80 threads finish 8x10 outputs.
// ---------------------------------------------------------------------------
__global__ void __launch_bounds__(256) mlp_kernel(
    const float* __restrict__ fc1w, const float* __restrict__ fc1b,
    const float* __restrict__ fc2w, const float* __restrict__ fc2b,
    float* __restrict__ out)
{
    __shared__ float zt[8 * ZDIM];
    __shared__ float ys[8 * 65];
    int tid = threadIdx.x;
    int bbase = blockIdx.x * 8;

    for (int i = tid; i < 8 * ZDIM; i += 256)
        zt[i] = z_buf[bbase * ZDIM + i];
    __syncthreads();

    int j = tid & 63, g = tid >> 6;          // g = 0..3
    const float* z0 = zt + (g * 2) * ZDIM;
    const float* z1 = z0 + ZDIM;
    float acc0 = 0.0f, acc1 = 0.0f;
    #pragma unroll 4
    for (int i = 0; i < ZDIM; i++) {
        float wv = fc1w[i * 64 + j];
        acc0 += z0[i] * wv;
        acc1 += z1[i] * wv;
    }
    float bj = fc1b[j];
    ys[(g * 2) * 65 + j]     = fmaxf(acc0 + bj, 0.0f);
    ys[(g * 2 + 1) * 65 + j] = fmaxf(acc1 + bj, 0.0f);
    __syncthreads();

    if (tid < 80) {
        int s = tid / 10, k = tid - s * 10;
        float acc = fc2b[k];
        #pragma unroll
        for (int jj = 0; jj < 64; jj++)
            acc += ys[s * 65 + jj] * fc2w[jj * 10 + k];
        out[(bbase + s) * 10 + k] = acc;
    }
}

// ---------------------------------------------------------------------------
extern "C" void kernel_launch(void* const* d_in, const int* in_sizes, int n_in,
                              void* d_out, int out_size)
{
    const float* x    = (const float*)d_in[0];
    const float* dtm1 = (const float*)d_in[1];
    const float* dtm2 = (const float*)d_in[2];
    const float* w1   = (const float*)d_in[3];
    const float* b1   = (const float*)d_in[4];
    const float* w2   = (const float*)d_in[5];
    const float* b2   = (const float*)d_in[6];
    const float* g1w  = (const float*)d_in[7];
    const float* g1b  = (const float*)d_in[8];
    const float* g2w  = (const float*)d_in[9];
    const float* g2b  = (const float*)d_in[10];
    const float* fc1w = (const float*)d_in[11];
    const float* fc1b = (const float*)d_in[12];
    const float* fc2w = (const float*)d_in[13];
    const float* fc2b = (const float*)d_in[14];
    float* out = (float*)d_out;

    cudaFuncSetAttribute(conv_kernel, cudaFuncAttributeMaxDynamicSharedMemorySize,
                         SMEM_FLOATS * (int)sizeof(float));

    tda_kernel<<<NB, 128>>>(dtm1, dtm2, g1w, g1b, g2w, g2b);
    conv_kernel<<<NB, 256, SMEM_FLOATS * sizeof(float)>>>(x, w1, b1, w2, b2);
    mlp_kernel<<<NB / 8, 256>>>(fc1w, fc1b, fc2w, fc2b, out);
}

// round 4
// speedup vs baseline: 1.1506x; 1.1506x over previous
#include <cuda_runtime.h>

#define NB 1024
#define PIX 784
#define ZDIM 848

// Scratch: concat buffer z = [hf(784) | x1(32) | x2(32)] per sample
__device__ float z_buf[NB * ZDIM];

// ---------------------------------------------------------------------------
// Kernel 1: TDA branches. Landscape top-k collapses to (max, min1, min2).
// Vectorized float4 loads (784 = 196 float4).
// ---------------------------------------------------------------------------
__global__ void __launch_bounds__(128) tda_kernel(
    const float* __restrict__ dtm1, const float* __restrict__ dtm2,
    const float* __restrict__ g1w, const float* __restrict__ g1b,
    const float* __restrict__ g2w, const float* __restrict__ g2b)
{
    int b = blockIdx.x;
    int tid = threadIdx.x;
    const float4* v1 = (const float4*)(dtm1 + b * PIX);
    const float4* v2 = (const float4*)(dtm2 + b * PIX);

    float mx1 = -1e30f, a1 = 1e30f, a2 = 1e30f;
    float mx2 = -1e30f, c1 = 1e30f, c2 = 1e30f;
    for (int i = tid; i < 196; i += 128) {
        float4 u4 = v1[i];
        float4 w4 = v2[i];
        #pragma unroll
        for (int j = 0; j < 4; j++) {
            float u = (j == 0) ? u4.x : (j == 1) ? u4.y : (j == 2) ? u4.z : u4.w;
            mx1 = fmaxf(mx1, u);
            if (u < a1) { a2 = a1; a1 = u; } else if (u < a2) a2 = u;
            float w = (j == 0) ? w4.x : (j == 1) ? w4.y : (j == 2) ? w4.z : w4.w;
            mx2 = fmaxf(mx2, w);
            if (w < c1) { c2 = c1; c1 = w; } else if (w < c2) c2 = w;
        }
    }
    #pragma unroll
    for (int off = 16; off; off >>= 1) {
        mx1 = fmaxf(mx1, __shfl_xor_sync(~0u, mx1, off));
        float o1 = __shfl_xor_sync(~0u, a1, off);
        float o2 = __shfl_xor_sync(~0u, a2, off);
        float n1 = fminf(a1, o1);
        float n2 = fminf(fmaxf(a1, o1), fminf(a2, o2));
        a1 = n1; a2 = n2;
        mx2 = fmaxf(mx2, __shfl_xor_sync(~0u, mx2, off));
        float p1 = __shfl_xor_sync(~0u, c1, off);
        float p2 = __shfl_xor_sync(~0u, c2, off);
        float q1 = fminf(c1, p1);
        float q2 = fminf(fmaxf(c1, p1), fminf(c2, p2));
        c1 = q1; c2 = q2;
    }
    __shared__ float red[4][6];
    __shared__ float fin[6];
    if ((tid & 31) == 0) {
        int w = tid >> 5;
        red[w][0] = mx1; red[w][1] = a1; red[w][2] = a2;
        red[w][3] = mx2; red[w][4] = c1; red[w][5] = c2;
    }
    __syncthreads();
    if (tid == 0) {
        float M1 = red[0][0], A1 = red[0][1], A2 = red[0][2];
        float M2 = red[0][3], C1 = red[0][4], C2 = red[0][5];
        #pragma unroll
        for (int w = 1; w < 4; w++) {
            M1 = fmaxf(M1, red[w][0]);
            float o1 = red[w][1], o2 = red[w][2];
            float n1 = fminf(A1, o1);
            float n2 = fminf(fmaxf(A1, o1), fminf(A2, o2));
            A1 = n1; A2 = n2;
            M2 = fmaxf(M2, red[w][3]);
            float p1 = red[w][4], p2 = red[w][5];
            float q1 = fminf(C1, p1);
            float q2 = fminf(fmaxf(C1, p1), fminf(C2, p2));
            C1 = q1; C2 = q2;
        }
        fin[0] = M1; fin[1] = A1; fin[2] = A2;
        fin[3] = M2; fin[4] = C1; fin[5] = C2;
    }
    __syncthreads();

    __shared__ float lam1[64], lam2[64];
    if (tid < 64) {
        int k = tid >> 5, t = tid & 31;
        float tv1 = 0.01f + (float)t * (0.28f / 31.0f);
        float tv2 = 0.05f + (float)t * (0.25f / 31.0f);
        float m1 = k ? fin[2] : fin[1];
        float m2 = k ? fin[5] : fin[4];
        lam1[tid] = fmaxf(0.0f, fminf(tv1 - m1, fin[0] - tv1));
        lam2[tid] = fmaxf(0.0f, fminf(tv2 - m2, fin[3] - tv2));
    }
    __syncthreads();

    if (tid < 32) {
        float acc = g1b[tid];
        #pragma unroll
        for (int i = 0; i < 64; i++) acc += lam1[i] * g1w[i * 32 + tid];
        z_buf[b * ZDIM + 784 + tid] = fmaxf(acc, 0.0f);
    } else if (tid < 64) {
        int j = tid - 32;
        float acc = g2b[j];
        #pragma unroll
        for (int i = 0; i < 64; i++) acc += lam2[i] * g2w[i * 32 + j];
        z_buf[b * ZDIM + 816 + j] = fmaxf(acc, 0.0f);
    }
}

// ---------------------------------------------------------------------------
// Kernel 2: fused conv1+ReLU+conv2+ReLU, factorized.
//   conv2(out[p] = sum_{k,c} h1[p+d_k,c] w2[k,c]) is computed as
//   F[q,k] = sum_c h1[q,c] w2[k,c]  (pointwise 32x9 GEMM per pixel), then
//   out[p] = b2 + sum_k F[p+d_k, k] (9-point gather).
// Row-split: blockIdx.y selects 14-row half; h1/F computed for 16 local rows.
// smem: xs[18*32] | h1[448*36] | F[448*9]
// ---------------------------------------------------------------------------
#define XS_FL   (18 * 32)
#define H1_FL   (448 * 36)
#define F_FL    (448 * 9)
#define CSMEM_FLOATS (XS_FL + H1_FL + F_FL)

__global__ void __launch_bounds__(256, 2) conv_kernel(
    const float* __restrict__ x,
    const float* __restrict__ w1, const float* __restrict__ b1,
    const float* __restrict__ w2, const float* __restrict__ b2)
{
    extern __shared__ float smem[];
    float* xs = smem;             // 18 rows x 32 cols, zero-padded
    float* h1 = smem + XS_FL;     // [local_pixel][c], stride 36 (16B aligned, conflict-free)
    float* Fb = h1 + H1_FL;       // [local_pixel][k], stride 9

    int b = blockIdx.x;
    int base = 14 * blockIdx.y;   // output row base (0 or 14)
    int tid = threadIdx.x;

    // ---- load x tile: global rows base-2 .. base+15, cols -1..28, zero halo
    for (int i = tid; i < XS_FL; i += 256) {
        int r = i >> 5, c = i & 31;
        int gr = base - 2 + r, gc = c - 1;
        float v = 0.0f;
        if (gr >= 0 && gr < 28 && gc >= 0 && gc < 28 && c < 30)
            v = x[b * 784 + gr * 28 + gc];
        xs[i] = v;
    }
    __syncthreads();

    // ---- conv1: lane = channel c, warp = pixel-group (2 rows each)
    {
        int c = tid & 31;
        int pg = tid >> 5;             // 0..7
        float wk[9];
        #pragma unroll
        for (int k = 0; k < 9; k++) wk[k] = w1[k * 32 + c];   // coalesced LDG
        float bc = b1[c];

        #pragma unroll
        for (int half = 0; half < 2; half++) {
            int lr = pg * 2 + half;                 // local h1 row 0..15
            const float* xr = xs + lr * 32;
            // sliding 3x3 window (broadcast LDS, 3 new values per pixel)
            float a0 = xr[0],      b0 = xr[1];
            float a1v = xr[32],    b1v = xr[33];
            float a2v = xr[64],    b2v = xr[65];
            float* hrow = h1 + lr * 28 * 36 + c;
            #pragma unroll 4
            for (int col = 0; col < 28; col++) {
                float c0 = xr[col + 2];
                float c1v = xr[32 + col + 2];
                float c2v = xr[64 + col + 2];
                float acc = bc;
                acc += a0  * wk[0]; acc += b0  * wk[1]; acc += c0  * wk[2];
                acc += a1v * wk[3]; acc += b1v * wk[4]; acc += c1v * wk[5];
                acc += a2v * wk[6]; acc += b2v * wk[7]; acc += c2v * wk[8];
                hrow[col * 36] = fmaxf(acc, 0.0f);
                a0 = b0;  b0 = c0;
                a1v = b1v; b1v = c1v;
                a2v = b2v; b2v = c2v;
            }
        }
    }
    __syncthreads();

    // ---- F-pass: thread = (tap k, column pg); w2 row hoisted to 32 regs
    if (tid < 252) {
        int k = tid / 28, pgc = tid % 28;
        float wc[32];
        #pragma unroll
        for (int c = 0; c < 32; c++) wc[c] = w2[k * 32 + c];
        #pragma unroll 2
        for (int i = 0; i < 16; i++) {
            int lp = i * 28 + pgc;
            const float4* hp = (const float4*)(h1 + lp * 36);
            float s0 = 0.0f, s1 = 0.0f, s2 = 0.0f, s3 = 0.0f;
            #pragma unroll
            for (int j = 0; j < 8; j++) {
                float4 v = hp[j];
                s0 += v.x * wc[4 * j + 0];
                s1 += v.y * wc[4 * j + 1];
                s2 += v.z * wc[4 * j + 2];
                s3 += v.w * wc[4 * j + 3];
            }
            Fb[lp * 9 + k] = (s0 + s1) + (s2 + s3);
        }
    }
    __syncthreads();

    // ---- gather: out[p] = relu(b2 + sum_k F[p + d_k, k])
    float b2v = b2[0];
    for (int o = tid; o < 14 * 28; o += 256) {
        int r = o / 28, oc = o - r * 28;
        int orow = base + r;
        float acc = b2v;
        #pragma unroll
        for (int dy = 0; dy < 3; dy++) {
            int gr = orow + dy - 1;
            if (gr < 0 || gr >= 28) continue;
            int lrn = r + dy;              // local F row 0..15
            #pragma unroll
            for (int dx = 0; dx < 3; dx++) {
                int nc = oc + dx - 1;
                if (nc < 0 || nc >= 28) continue;
                acc += Fb[(lrn * 28 + nc) * 9 + dy * 3 + dx];
            }
        }
        z_buf[b * ZDIM + orow * 28 + oc] = fmaxf(acc, 0.0f);
    }
}

// ---------------------------------------------------------------------------
// Kernel 3: MLP head. 8 samples/block, 256 threads.
// ---------------------------------------------------------------------------
__global__ void __launch_bounds__(256) mlp_kernel(
    const float* __restrict__ fc1w, const float* __restrict__ fc1b,
    const float* __restrict__ fc2w, const float* __restrict__ fc2b,
    float* __restrict__ out)
{
    __shared__ float zt[8 * ZDIM];
    __shared__ float ys[8 * 65];
    int tid = threadIdx.x;
    int bbase = blockIdx.x * 8;

    const float4* src = (const float4*)(z_buf + bbase * ZDIM);
    float4* dst = (float4*)zt;
    for (int i = tid; i < 8 * ZDIM / 4; i += 256)
        dst[i] = src[i];
    __syncthreads();

    int j = tid & 63, g = tid >> 6;          // g = 0..3
    const float* z0 = zt + (g * 2) * ZDIM;
    const float* z1 = z0 + ZDIM;
    float acc0 = 0.0f, acc1 = 0.0f;
    #pragma unroll 4
    for (int i = 0; i < ZDIM; i++) {
        float wv = fc1w[i * 64 + j];
        acc0 += z0[i] * wv;
        acc1 += z1[i] * wv;
    }
    float bj = fc1b[j];
    ys[(g * 2) * 65 + j]     = fmaxf(acc0 + bj, 0.0f);
    ys[(g * 2 + 1) * 65 + j] = fmaxf(acc1 + bj, 0.0f);
    __syncthreads();

    if (tid < 80) {
        int s = tid / 10, k = tid - s * 10;
        float acc = fc2b[k];
        #pragma unroll
        for (int jj = 0; jj < 64; jj++)
            acc += ys[s * 65 + jj] * fc2w[jj * 10 + k];
        out[(bbase + s) * 10 + k] = acc;
    }
}

// ---------------------------------------------------------------------------
extern "C" void kernel_launch(void* const* d_in, const int* in_sizes, int n_in,
                              void* d_out, int out_size)
{
    const float* x    = (const float*)d_in[0];
    const float* dtm1 = (const float*)d_in[1];
    const float* dtm2 = (const float*)d_in[2];
    const float* w1   = (const float*)d_in[3];
    const float* b1   = (const float*)d_in[4];
    const float* w2   = (const float*)d_in[5];
    const float* b2   = (const float*)d_in[6];
    const float* g1w  = (const float*)d_in[7];
    const float* g1b  = (const float*)d_in[8];
    const float* g2w  = (const float*)d_in[9];
    const float* g2b  = (const float*)d_in[10];
    const float* fc1w = (const float*)d_in[11];
    const float* fc1b = (const float*)d_in[12];
    const float* fc2w = (const float*)d_in[13];
    const float* fc2b = (const float*)d_in[14];
    float* out = (float*)d_out;

    cudaFuncSetAttribute(conv_kernel, cudaFuncAttributeMaxDynamicSharedMemorySize,
                         CSMEM_FLOATS * (int)sizeof(float));

    tda_kernel<<<NB, 128>>>(dtm1, dtm2, g1w, g1b, g2w, g2b);
    conv_kernel<<<dim3(NB, 2), 256, CSMEM_FLOATS * sizeof(float)>>>(x, w1, b1, w2, b2);
    mlp_kernel<<<NB / 8, 256>>>(fc1w, fc1b, fc2w, fc2b, out);
}